// round 14
// baseline (speedup 1.0000x reference)
#include <cuda_runtime.h>
#include <cuda_bf16.h>

// Problem constants
#define B_    64
#define C_    2048
#define HW_   576
#define HW4_  144          // HW_/4 float4 groups per channel row
#define NBLK  32           // k1 tiles per (t,b): 64 channels each
#define CPS   16           // channels per (block, csub)
#define NCLS  16           // NUM_CLASSES

// Accumulator layout inside one parity buffer (floats):
#define LUMV_OFF 0                       // [B_][HW_] lum_v
#define LUMI_OFF (B_ * HW_)              // [B_][HW_] lum_i
#define CLSU_OFF (2 * B_ * HW_)          // [NCLS][HW_] sum of lum_v per class
#define CLSW_OFF (2 * B_ * HW_ + NCLS * HW_)  // [NCLS][HW_] sum of lum_i per class
#define ACCTOT   (2 * B_ * HW_ + 2 * NCLS * HW_)   // 92160 floats

// Scratch (allocation-free rule: __device__ globals; zero at module load).
// Parity ping-pong: k1(N) accumulates acc[par], zeroes acc[1-par];
// k2(N) reads acc[par], flips par. Invariant: acc[par] is zero when k1 starts.
__device__ float        g_acc[2][ACCTOT];
__device__ int          g_parity;
__device__ double       g_sum;
__device__ int          g_cnt;
__device__ unsigned int g_ticket;

// ---------------------------------------------------------------------------
// Kernel 1: streaming sum-of-squares (frozen pattern), float4 loads, smem
// fold, REDG.F32 atomicAdd of per-tile fold into BOTH the per-row lum and
// the per-class sum vector (class sums are linear in lum -> built for free).
// Zeroes other parity buffer (23 floats/block) + scalar reduction state.
// grid = (NBLK, B, 2) = 4096 blocks, block = 576, 3 blocks/SM.
// ---------------------------------------------------------------------------
__global__ void __launch_bounds__(576, 3)
k_lum_partial(const float* __restrict__ fv, const float* __restrict__ fi,
              const int* __restrict__ labels) {
    const int blk  = blockIdx.x;
    const int b    = blockIdx.y;
    const int t    = blockIdx.z;
    const int tid  = threadIdx.x;
    const int q    = tid % HW4_;
    const int csub = tid / HW4_;

    const int par = g_parity;

    if (blk == 0 && b == 0 && t == 0 && tid == 0) {
        g_sum = 0.0; g_cnt = 0; g_ticket = 0u;
    }

    // Zero the other parity buffer: 92160 floats over 4096 blocks = 23 each.
    {
        const int blin = blk + NBLK * (b + B_ * t);   // 0..4095
        const int idx  = blin * 23 + tid;
        if (tid < 23 && idx < ACCTOT) g_acc[1 - par][idx] = 0.0f;
    }

    const float* __restrict__ f = t ? fi : fv;
    const float4* __restrict__ base = (const float4*)
        (f + ((size_t)b * C_ + (size_t)blk * 64) * HW_)
        + (size_t)csub * CPS * HW4_ + q;

    float ax = 0.f, ay = 0.f, az = 0.f, aw = 0.f;
#pragma unroll 8
    for (int it = 0; it < CPS; ++it) {
        float4 x = base[(size_t)it * HW4_];
        ax = fmaf(x.x, x.x, ax);
        ay = fmaf(x.y, x.y, ay);
        az = fmaf(x.z, x.z, az);
        aw = fmaf(x.w, x.w, aw);
    }

    __shared__ float4 sh[4][HW4_];
    sh[csub][q] = make_float4(ax, ay, az, aw);
    __syncthreads();

    if (csub == 0) {
        float4 a = sh[0][q], c1 = sh[1][q], c2 = sh[2][q], c3 = sh[3][q];
        a.x += c1.x + c2.x + c3.x;
        a.y += c1.y + c2.y + c3.y;
        a.z += c1.z + c2.z + c3.z;
        a.w += c1.w + c2.w + c3.w;

        const int lab = labels[b];
        float* accp = g_acc[par];
        float* dst  = accp + (t == 0 ? LUMV_OFF : LUMI_OFF) + b * HW_ + 4 * q;
        float* cdst = accp + (t == 0 ? CLSU_OFF : CLSW_OFF) + lab * HW_ + 4 * q;
        atomicAdd(dst + 0, a.x);  atomicAdd(cdst + 0, a.x);
        atomicAdd(dst + 1, a.y);  atomicAdd(cdst + 1, a.y);
        atomicAdd(dst + 2, a.z);  atomicAdd(cdst + 2, a.z);
        atomicAdd(dst + 3, a.w);  atomicAdd(cdst + 3, a.w);
    }
}

// ---------------------------------------------------------------------------
// Kernel 2: class-factored finish. grid = 64, block = 576 (18 warps).
// total_raw = sum_i (n_i-1)*(|lv_i|^2 + |li_i|^2) + 2*sum_i lv_i.li_i
//           - 2*sum_c U_c.W_c          (U_c, W_c = class-sum vectors)
// loss = total_raw / HW / npairs,  npairs = sum_i (n_i - 1).
// Block i: 3-way dot over its own row (thread p = tid), n_i count via
// __syncthreads_count; blocks 0..15 also do the class dot. All double.
// Ticket block finalizes + flips parity. Labels are int32 (JAX x64 off).
// ---------------------------------------------------------------------------
__global__ void __launch_bounds__(576, 2)
k_finish(const int* __restrict__ labels, float* __restrict__ out) {
    const int i    = blockIdx.x;   // 0..63
    const int tid  = threadIdx.x;  // 0..575
    const int lane = tid & 31;
    const int wid  = tid >> 5;     // 0..17

    const int par = g_parity;
    const float* __restrict__ acc = g_acc[par];

    // per-row triple dot (thread p = tid)
    const double lv = (double)acc[LUMV_OFF + i * HW_ + tid];
    const double li = (double)acc[LUMI_OFF + i * HW_ + tid];
    double v2 = lv * lv;
    double i2 = li * li;
    double dd = lv * li;

    // class dot (blocks 0..15 double as class c = i)
    double uw = 0.0;
    if (i < NCLS) {
        const double u = (double)acc[CLSU_OFF + i * HW_ + tid];
        const double w = (double)acc[CLSW_OFF + i * HW_ + tid];
        uw = u * w;
    }

#pragma unroll
    for (int off = 16; off > 0; off >>= 1) {
        v2 += __shfl_down_sync(0xffffffffu, v2, off);
        i2 += __shfl_down_sync(0xffffffffu, i2, off);
        dd += __shfl_down_sync(0xffffffffu, dd, off);
        uw += __shfl_down_sync(0xffffffffu, uw, off);
    }

    __shared__ double s_v2[18], s_i2[18], s_dd[18], s_uw[18];
    if (lane == 0) { s_v2[wid] = v2; s_i2[wid] = i2; s_dd[wid] = dd; s_uw[wid] = uw; }

    // n_i = |{j : labels[j] == labels[i]}| (includes i)
    const bool m = (tid < B_) && (labels[tid] == labels[i]);
    const int n_i = __syncthreads_count(m);   // also orders s_* writes

    if (tid == 0) {
        double V2 = 0.0, I2 = 0.0, DD = 0.0, UW = 0.0;
#pragma unroll
        for (int k = 0; k < 18; ++k) {
            V2 += s_v2[k]; I2 += s_i2[k]; DD += s_dd[k]; UW += s_uw[k];
        }
        double contrib = (double)(n_i - 1) * (V2 + I2) + 2.0 * DD;
        if (i < NCLS) contrib -= 2.0 * UW;

        atomicAdd(&g_sum, contrib);
        atomicAdd(&g_cnt, n_i - 1);
        __threadfence();
        const unsigned tk = atomicAdd(&g_ticket, 1u);
        if (tk == B_ - 1) {
            const double total = atomicAdd(&g_sum, 0.0);  // atomic read
            const int    cnt   = atomicAdd(&g_cnt, 0);    // npairs
            out[0] = (cnt > 0)
                   ? (float)(total / (double)HW_ / (double)cnt) : 0.0f;
            g_parity = par ^ 1;                           // flip for next replay
            __threadfence();
        }
    }
}

extern "C" void kernel_launch(void* const* d_in, const int* in_sizes, int n_in,
                              void* d_out, int out_size) {
    const float* fv     = (const float*)d_in[0];
    const float* fi     = (const float*)d_in[1];
    const int*   labels = (const int*)d_in[2];
    float*       out    = (float*)d_out;

    k_lum_partial<<<dim3(NBLK, B_, 2), 576>>>(fv, fi, labels);
    k_finish<<<B_, 576>>>(labels, out);
}